// round 2
// baseline (speedup 1.0000x reference)
#include <cuda_runtime.h>
#include <math.h>

#define S_   16
#define B_   8
#define H_   16
#define DH_  64
#define D_   1024
#define LC_  8192
#define LT_  8208          // LC_ + S_
#define CH_  128           // timestep chunk
#define NCH_ 65            // ceil(LT_/CH_)
#define KSTR_ 68           // padded smem row stride (floats) for K/V
#define PSTR_ 132          // padded smem row stride for scores
#define ROWSTRIDE_ 8192    // B_*H_*DH_ floats per timestep
#define KOFF_ 131072                   // res elements
#define VOFF_ (131072 + 67239936)      // res + new_k elements

// scratch (allocation-free rule: device globals)
__device__ float g_q[S_ * B_ * D_];
__device__ float g_ctx[S_ * B_ * D_];

// ---------------- cp.async helpers ----------------
__device__ __forceinline__ void cp_async16(unsigned saddr, const void* gptr) {
    asm volatile("cp.async.cg.shared.global [%0], [%1], 16;" :: "r"(saddr), "l"(gptr));
}
__device__ __forceinline__ void cp_commit() {
    asm volatile("cp.async.commit_group;" ::: "memory");
}
template <int N> __device__ __forceinline__ void cp_wait() {
    asm volatile("cp.async.wait_group %0;" :: "n"(N) : "memory");
}
__device__ __forceinline__ unsigned smem_u32(const void* p) {
    return (unsigned)__cvta_generic_to_shared(p);
}

// ---------------- QKV projection ----------------
// x:(128,1024) @ W:(1024,1024) for Wq/Wk/Wv (blockIdx.z selects).
// q -> g_q ; k_new/v_new scattered into d_out new_k/new_v at timesteps LC_+s.
__global__ void __launch_bounds__(256)
qkv_kernel(const float* __restrict__ x,
           const float* __restrict__ Wq, const float* __restrict__ Wk,
           const float* __restrict__ Wv, float* __restrict__ out)
{
    const int mat = blockIdx.z;
    const float* __restrict__ W = (mat == 0) ? Wq : (mat == 1) ? Wk : Wv;
    const int r0 = blockIdx.y * 16;
    const int c0 = blockIdx.x * 64;

    __shared__ __align__(16) float As[16][KSTR_];
    __shared__ __align__(16) float Ws[64][KSTR_];

    const int tid = threadIdx.x;
    const int r  = tid & 15;    // output row in tile
    const int c4 = tid >> 4;    // output col group (4 cols)

    float ax = 0.f, ay = 0.f, az = 0.f, aw = 0.f;

    for (int k0 = 0; k0 < D_; k0 += 64) {
        {   // stage A tile 16x64
            const int rr = tid >> 4, cc = (tid & 15) << 2;
            const float4 v = *(const float4*)&x[(size_t)(r0 + rr) * D_ + k0 + cc];
            *(float4*)&As[rr][cc] = v;
        }
        #pragma unroll
        for (int i = 0; i < 4; ++i) {   // stage W tile 64x64
            const int rr = i * 16 + (tid >> 4), cc = (tid & 15) << 2;
            const float4 v = *(const float4*)&W[(size_t)(k0 + rr) * D_ + c0 + cc];
            *(float4*)&Ws[rr][cc] = v;
        }
        __syncthreads();
        #pragma unroll
        for (int kk = 0; kk < 64; ++kk) {
            const float a  = As[r][kk];
            const float4 w = *(const float4*)&Ws[kk][c4 << 2];
            ax += a * w.x; ay += a * w.y; az += a * w.z; aw += a * w.w;
        }
        __syncthreads();
    }

    const int row = r0 + r;            // row = s*B + b
    const int s = row >> 3, b = row & 7;
    const int col = c0 + (c4 << 2);
    const float4 res = make_float4(ax, ay, az, aw);
    if (mat == 0) {
        *(float4*)&g_q[(size_t)row * D_ + col] = res;
    } else {
        float* dst = out + ((mat == 1) ? KOFF_ : VOFF_);
        *(float4*)&dst[(size_t)(LC_ + s) * ROWSTRIDE_ + b * D_ + col] = res;
    }
}

// ---------------- fused attention + cache copy ----------------
// 1 CTA per (b,h). Online softmax over 65 chunks of 128 timesteps.
// K/V chunks double-buffered via cp.async; cache chunks written through to out.
__global__ void __launch_bounds__(256, 1)
attn_kernel(const float* __restrict__ cK, const float* __restrict__ cV,
            float* __restrict__ out)
{
    extern __shared__ __align__(16) float sh[];
    float* sQ  = sh;                       // 16*64
    float* sK0 = sQ  + S_ * DH_;           // 128*KSTR_
    float* sV0 = sK0 + CH_ * KSTR_;
    float* sK1 = sV0 + CH_ * KSTR_;
    float* sV1 = sK1 + CH_ * KSTR_;
    float* sP  = sV1 + CH_ * KSTR_;        // 16*PSTR_
    float* sM  = sP  + S_ * PSTR_;
    float* sL  = sM + 16;
    float* sF  = sL + 16;

    const int tid = threadIdx.x;
    const int bh  = blockIdx.x;            // b*H_ + h
    const int b   = bh >> 4, h = bh & 15;
    const int ts  = tid >> 4;              // query row 0..15
    const int tt  = tid & 15;

    {   // load Q, pre-scaled by 1/sqrt(DH)
        const float4 q4 = *(const float4*)&g_q[(size_t)(ts * B_ + b) * D_ + h * DH_ + (tt << 2)];
        float* dst = &sQ[ts * DH_ + (tt << 2)];
        dst[0] = q4.x * 0.125f; dst[1] = q4.y * 0.125f;
        dst[2] = q4.z * 0.125f; dst[3] = q4.w * 0.125f;
    }
    if (tid < 16) { sM[tid] = -1e30f; sL[tid] = 0.f; }

    float accx = 0.f, accy = 0.f, accz = 0.f, accw = 0.f;
    float* outK = out + KOFF_;
    float* outV = out + VOFF_;
    const size_t baseBH = (size_t)bh * DH_;

    auto issue = [&](int c, float* dK, float* dV) {
        const int t0 = c * CH_;
        const int n = (t0 + CH_ <= LT_ ? CH_ : LT_ - t0) * 16;
        for (int idx = tid; idx < n; idx += 256) {
            const int r = idx >> 4, f = (idx & 15) << 2;
            const int t = t0 + r;
            const size_t g = (size_t)t * ROWSTRIDE_ + baseBH + f;
            const float* srcK = (t < LC_) ? (cK + g) : (outK + g);
            const float* srcV = (t < LC_) ? (cV + g) : (outV + g);
            cp_async16(smem_u32(&dK[r * KSTR_ + f]), srcK);
            cp_async16(smem_u32(&dV[r * KSTR_ + f]), srcV);
        }
        cp_commit();
    };

    issue(0, sK0, sV0);
    __syncthreads();

    for (int c = 0; c < NCH_; ++c) {
        float* bK = (c & 1) ? sK1 : sK0;
        float* bV = (c & 1) ? sV1 : sV0;
        if (c + 1 < NCH_) {
            issue(c + 1, (c & 1) ? sK0 : sK1, (c & 1) ? sV0 : sV1);
            cp_wait<1>();
        } else {
            cp_wait<0>();
        }
        __syncthreads();

        const int t0   = c * CH_;
        const int rows = (t0 + CH_ <= LT_) ? CH_ : (LT_ - t0);

        // write-through copy of cache chunk (t < LC_ only; tail written by qkv_kernel)
        if (t0 < LC_) {
            for (int idx = tid; idx < CH_ * 16; idx += 256) {
                const int r = idx >> 4, f = (idx & 15) << 2;
                const size_t g = (size_t)(t0 + r) * ROWSTRIDE_ + baseBH + f;
                *(float4*)&outK[g] = *(const float4*)&bK[r * KSTR_ + f];
                *(float4*)&outV[g] = *(const float4*)&bV[r * KSTR_ + f];
            }
        }

        // scores: thread (ts,tt) does t = tt + 16j
        {
            const float* qr = &sQ[ts * DH_];
            #pragma unroll
            for (int j = 0; j < 8; ++j) {
                const int t = tt + (j << 4);
                if (t < rows) {
                    float sc;
                    if (t0 + t - LC_ <= ts) {     // causal (always true for t < LC_)
                        const float* kr = &bK[t * KSTR_];
                        float a0 = 0.f, a1 = 0.f, a2 = 0.f, a3 = 0.f;
                        #pragma unroll
                        for (int d = 0; d < DH_; d += 4) {
                            const float4 q4 = *(const float4*)&qr[d];
                            const float4 k4 = *(const float4*)&kr[d];
                            a0 += q4.x * k4.x; a1 += q4.y * k4.y;
                            a2 += q4.z * k4.z; a3 += q4.w * k4.w;
                        }
                        sc = (a0 + a1) + (a2 + a3);
                    } else sc = -1e30f;
                    sP[ts * PSTR_ + t] = sc;
                }
            }
        }
        __syncthreads();

        // online softmax update: 16 lanes per query row
        {
            float lm = -1e30f;
            #pragma unroll
            for (int j = 0; j < 8; ++j) {
                const int t = tt + (j << 4);
                if (t < rows) lm = fmaxf(lm, sP[ts * PSTR_ + t]);
            }
            #pragma unroll
            for (int o = 8; o >= 1; o >>= 1)
                lm = fmaxf(lm, __shfl_xor_sync(0xffffffffu, lm, o));
            const float mold = sM[ts];
            const float mnew = fmaxf(mold, lm);
            float ls = 0.f;
            #pragma unroll
            for (int j = 0; j < 8; ++j) {
                const int t = tt + (j << 4);
                if (t < rows) {
                    const float p = __expf(sP[ts * PSTR_ + t] - mnew);
                    sP[ts * PSTR_ + t] = p;
                    ls += p;
                }
            }
            #pragma unroll
            for (int o = 8; o >= 1; o >>= 1)
                ls += __shfl_xor_sync(0xffffffffu, ls, o);
            if (tt == 0) {
                const float fac = __expf(mold - mnew);
                sL[ts] = sL[ts] * fac + ls;
                sM[ts] = mnew;
                sF[ts] = fac;
            }
        }
        __syncthreads();

        // PV: thread (ts,tt) owns ctx[ts][tt*4 .. tt*4+3]
        {
            const float fac = sF[ts];
            accx *= fac; accy *= fac; accz *= fac; accw *= fac;
            const float* pr = &sP[ts * PSTR_];
            const int f = tt << 2;
            for (int t = 0; t < rows; t += 4) {
                #pragma unroll
                for (int u = 0; u < 4; ++u) {
                    const float p  = pr[t + u];
                    const float4 v4 = *(const float4*)&bV[(t + u) * KSTR_ + f];
                    accx += p * v4.x; accy += p * v4.y;
                    accz += p * v4.z; accw += p * v4.w;
                }
            }
        }
        __syncthreads();   // protect bK/bV/sP before next issue overwrites
    }

    const float inv = 1.f / sL[ts];
    *(float4*)&g_ctx[(size_t)(ts * B_ + b) * D_ + h * DH_ + (tt << 2)] =
        make_float4(accx * inv, accy * inv, accz * inv, accw * inv);
}

// ---------------- output projection: res = ctx @ Wo ----------------
__global__ void __launch_bounds__(256)
oproj_kernel(const float* __restrict__ Wo, float* __restrict__ out)
{
    const int r0 = blockIdx.y * 16;
    const int c0 = blockIdx.x * 64;
    __shared__ __align__(16) float As[16][KSTR_];
    __shared__ __align__(16) float Ws[64][KSTR_];
    const int tid = threadIdx.x;
    const int r  = tid & 15;
    const int c4 = tid >> 4;
    float ax = 0.f, ay = 0.f, az = 0.f, aw = 0.f;
    for (int k0 = 0; k0 < D_; k0 += 64) {
        {
            const int rr = tid >> 4, cc = (tid & 15) << 2;
            const float4 v = *(const float4*)&g_ctx[(size_t)(r0 + rr) * D_ + k0 + cc];
            *(float4*)&As[rr][cc] = v;
        }
        #pragma unroll
        for (int i = 0; i < 4; ++i) {
            const int rr = i * 16 + (tid >> 4), cc = (tid & 15) << 2;
            const float4 v = *(const float4*)&Wo[(size_t)(k0 + rr) * D_ + c0 + cc];
            *(float4*)&Ws[rr][cc] = v;
        }
        __syncthreads();
        #pragma unroll
        for (int kk = 0; kk < 64; ++kk) {
            const float a  = As[r][kk];
            const float4 w = *(const float4*)&Ws[kk][c4 << 2];
            ax += a * w.x; ay += a * w.y; az += a * w.z; aw += a * w.w;
        }
        __syncthreads();
    }
    *(float4*)&out[(size_t)(r0 + r) * D_ + c0 + (c4 << 2)] =
        make_float4(ax, ay, az, aw);
}

#define SMEM_ATTN_BYTES ((S_*DH_ + 4*CH_*KSTR_ + S_*PSTR_ + 48) * 4)

extern "C" void kernel_launch(void* const* d_in, const int* in_sizes, int n_in,
                              void* d_out, int out_size)
{
    const float* x  = (const float*)d_in[0];
    const float* ck = (const float*)d_in[1];
    const float* cv = (const float*)d_in[2];
    const float* Wq = (const float*)d_in[3];
    const float* Wk = (const float*)d_in[4];
    const float* Wv = (const float*)d_in[5];
    const float* Wo = (const float*)d_in[6];
    float* out = (float*)d_out;

    cudaFuncSetAttribute(attn_kernel,
        cudaFuncAttributeMaxDynamicSharedMemorySize, SMEM_ATTN_BYTES);

    qkv_kernel<<<dim3(16, 8, 3), 256>>>(x, Wq, Wk, Wv, out);
    attn_kernel<<<B_ * H_, 256, SMEM_ATTN_BYTES>>>(ck, cv, out);
    oproj_kernel<<<dim3(16, 8), 256>>>(Wo, out);
}

// round 3
// speedup vs baseline: 1.9908x; 1.9908x over previous
#include <cuda_runtime.h>
#include <math.h>

#define S_   16
#define B_   8
#define H_   16
#define DH_  64
#define D_   1024
#define LC_  8192
#define LT_  8208          // LC_ + S_
#define CH_  128           // timestep chunk
#define NCH_ 65            // ceil(LT_/CH_)
#define KSTR_ 68           // padded smem row stride (floats) for K/V
#define PSTR_ 132          // padded smem row stride for scores
#define ROWSTRIDE_ 8192    // B_*H_*DH_ floats per timestep
#define KOFF_ 131072                   // res elements
#define VOFF_ (131072 + 67239936)      // res + new_k elements

// scratch (allocation-free rule: device globals)
__device__ float g_q[S_ * B_ * D_];
__device__ float g_ctx[S_ * B_ * D_];

// ---------------- cp.async helpers ----------------
__device__ __forceinline__ void cp_async16(unsigned saddr, const void* gptr) {
    asm volatile("cp.async.cg.shared.global [%0], [%1], 16;" :: "r"(saddr), "l"(gptr));
}
__device__ __forceinline__ void cp_commit() {
    asm volatile("cp.async.commit_group;" ::: "memory");
}
template <int N> __device__ __forceinline__ void cp_wait() {
    asm volatile("cp.async.wait_group %0;" :: "n"(N) : "memory");
}
__device__ __forceinline__ unsigned smem_u32(const void* p) {
    return (unsigned)__cvta_generic_to_shared(p);
}

// ---------------- tf32 mma helpers ----------------
__device__ __forceinline__ unsigned toTF32(float x) {
    unsigned r;
    asm("cvt.rna.tf32.f32 %0, %1;" : "=r"(r) : "f"(x));
    return r;
}
// D = A(16x8) * B(8x8) + D, tf32 inputs, f32 accum
__device__ __forceinline__ void mma_tf32(float& c0, float& c1, float& c2, float& c3,
                                         unsigned a0, unsigned a1, unsigned a2, unsigned a3,
                                         unsigned b0, unsigned b1) {
    asm volatile(
        "mma.sync.aligned.m16n8k8.row.col.f32.tf32.tf32.f32 "
        "{%0,%1,%2,%3},{%4,%5,%6,%7},{%8,%9},{%0,%1,%2,%3};"
        : "+f"(c0), "+f"(c1), "+f"(c2), "+f"(c3)
        : "r"(a0), "r"(a1), "r"(a2), "r"(a3), "r"(b0), "r"(b1));
}

// ---------------- QKV projection ----------------
__global__ void __launch_bounds__(256)
qkv_kernel(const float* __restrict__ x,
           const float* __restrict__ Wq, const float* __restrict__ Wk,
           const float* __restrict__ Wv, float* __restrict__ out)
{
    const int mat = blockIdx.z;
    const float* __restrict__ W = (mat == 0) ? Wq : (mat == 1) ? Wk : Wv;
    const int r0 = blockIdx.y * 16;
    const int c0 = blockIdx.x * 64;

    __shared__ __align__(16) float As[16][KSTR_];
    __shared__ __align__(16) float Ws[64][KSTR_];

    const int tid = threadIdx.x;
    const int r  = tid & 15;
    const int c4 = tid >> 4;

    float ax = 0.f, ay = 0.f, az = 0.f, aw = 0.f;

    for (int k0 = 0; k0 < D_; k0 += 64) {
        {
            const int rr = tid >> 4, cc = (tid & 15) << 2;
            const float4 v = *(const float4*)&x[(size_t)(r0 + rr) * D_ + k0 + cc];
            *(float4*)&As[rr][cc] = v;
        }
        #pragma unroll
        for (int i = 0; i < 4; ++i) {
            const int rr = i * 16 + (tid >> 4), cc = (tid & 15) << 2;
            const float4 v = *(const float4*)&W[(size_t)(k0 + rr) * D_ + c0 + cc];
            *(float4*)&Ws[rr][cc] = v;
        }
        __syncthreads();
        #pragma unroll
        for (int kk = 0; kk < 64; kk += 4) {
            const float4 a4 = *(const float4*)&As[r][kk];
            #pragma unroll
            for (int u = 0; u < 4; ++u) {
                const float a = (u == 0) ? a4.x : (u == 1) ? a4.y : (u == 2) ? a4.z : a4.w;
                const float4 w = *(const float4*)&Ws[kk + u][c4 << 2];
                ax += a * w.x; ay += a * w.y; az += a * w.z; aw += a * w.w;
            }
        }
        __syncthreads();
    }

    const int row = r0 + r;            // row = s*B + b
    const int s = row >> 3, b = row & 7;
    const int col = c0 + (c4 << 2);
    const float4 res = make_float4(ax, ay, az, aw);
    if (mat == 0) {
        *(float4*)&g_q[(size_t)row * D_ + col] = res;
    } else {
        float* dst = out + ((mat == 1) ? KOFF_ : VOFF_);
        *(float4*)&dst[(size_t)(LC_ + s) * ROWSTRIDE_ + b * D_ + col] = res;
    }
}

// ---------------- fused attention + cache copy (tf32 mma) ----------------
__global__ void __launch_bounds__(256, 1)
attn_kernel(const float* __restrict__ cK, const float* __restrict__ cV,
            float* __restrict__ out)
{
    extern __shared__ __align__(16) float sh[];
    float* sQ  = sh;                       // 16*64
    float* sK0 = sQ  + S_ * DH_;           // 128*KSTR_
    float* sV0 = sK0 + CH_ * KSTR_;
    float* sK1 = sV0 + CH_ * KSTR_;
    float* sV1 = sK1 + CH_ * KSTR_;
    float* sP  = sV1 + CH_ * KSTR_;        // 16*PSTR_
    float* sM  = sP  + S_ * PSTR_;
    float* sL  = sM + 16;
    float* sF  = sL + 16;

    const int tid  = threadIdx.x;
    const int lane = tid & 31;
    const int w    = tid >> 5;             // warp 0..7
    const int bh   = blockIdx.x;
    const int b    = bh >> 4, h = bh & 15;
    const int ts   = tid >> 4;             // softmax row mapping
    const int tt   = tid & 15;
    const int g    = lane >> 2;            // mma group row 0..7
    const int t4   = lane & 3;             // mma thread-in-group

    {   // load Q, pre-scaled by 1/sqrt(DH)
        const float4 q4 = *(const float4*)&g_q[(size_t)(ts * B_ + b) * D_ + h * DH_ + (tt << 2)];
        float* dst = &sQ[ts * DH_ + (tt << 2)];
        dst[0] = q4.x * 0.125f; dst[1] = q4.y * 0.125f;
        dst[2] = q4.z * 0.125f; dst[3] = q4.w * 0.125f;
    }
    if (tid < 16) { sM[tid] = -1e30f; sL[tid] = 0.f; }

    float* outK = out + KOFF_;
    float* outV = out + VOFF_;
    const size_t baseBH = (size_t)bh * DH_;

    auto issue = [&](int c, float* dK, float* dV) {
        const int t0 = c * CH_;
        const int n = (t0 + CH_ <= LT_ ? CH_ : LT_ - t0) * 16;
        for (int idx = tid; idx < n; idx += 256) {
            const int r = idx >> 4, f = (idx & 15) << 2;
            const int t = t0 + r;
            const size_t gg = (size_t)t * ROWSTRIDE_ + baseBH + f;
            const float* srcK = (t < LC_) ? (cK + gg) : (outK + gg);
            const float* srcV = (t < LC_) ? (cV + gg) : (outV + gg);
            cp_async16(smem_u32(&dK[r * KSTR_ + f]), srcK);
            cp_async16(smem_u32(&dV[r * KSTR_ + f]), srcV);
        }
        cp_commit();
    };

    issue(0, sK0, sV0);
    __syncthreads();    // sQ visible to all

    // Q fragments in registers (every warp holds full 16x64 Q)
    unsigned qA[8][4];
    #pragma unroll
    for (int ks = 0; ks < 8; ++ks) {
        qA[ks][0] = toTF32(sQ[g * DH_       + ks * 8 + t4]);
        qA[ks][1] = toTF32(sQ[(g + 8) * DH_ + ks * 8 + t4]);
        qA[ks][2] = toTF32(sQ[g * DH_       + ks * 8 + t4 + 4]);
        qA[ks][3] = toTF32(sQ[(g + 8) * DH_ + ks * 8 + t4 + 4]);
    }

    float oc0 = 0.f, oc1 = 0.f, oc2 = 0.f, oc3 = 0.f;   // PV accum (n = 8w..8w+7)

    for (int c = 0; c < NCH_; ++c) {
        float* bK = (c & 1) ? sK1 : sK0;
        float* bV = (c & 1) ? sV1 : sV0;
        if (c + 1 < NCH_) {
            issue(c + 1, (c & 1) ? sK0 : sK1, (c & 1) ? sV0 : sV1);
            cp_wait<1>();
        } else {
            cp_wait<0>();
        }
        __syncthreads();

        const int t0   = c * CH_;
        const int rows = (t0 + CH_ <= LT_) ? CH_ : (LT_ - t0);

        // write-through copy of cache chunk
        if (t0 < LC_) {
            for (int idx = tid; idx < CH_ * 16; idx += 256) {
                const int r = idx >> 4, f = (idx & 15) << 2;
                const size_t gg = (size_t)(t0 + r) * ROWSTRIDE_ + baseBH + f;
                *(float4*)&outK[gg] = *(const float4*)&bK[r * KSTR_ + f];
                *(float4*)&outV[gg] = *(const float4*)&bV[r * KSTR_ + f];
            }
        }

        // scores via mma: warp w computes cols [16w, 16w+16)
        #pragma unroll
        for (int nt = 0; nt < 2; ++nt) {
            const int n0 = (w << 4) + (nt << 3);
            float c0 = 0.f, c1 = 0.f, c2 = 0.f, c3 = 0.f;
            #pragma unroll
            for (int ks = 0; ks < 8; ++ks) {
                const unsigned b0 = toTF32(bK[(n0 + g) * KSTR_ + ks * 8 + t4]);
                const unsigned b1 = toTF32(bK[(n0 + g) * KSTR_ + ks * 8 + t4 + 4]);
                mma_tf32(c0, c1, c2, c3,
                         qA[ks][0], qA[ks][1], qA[ks][2], qA[ks][3], b0, b1);
            }
            *(float2*)&sP[g * PSTR_       + n0 + (t4 << 1)] = make_float2(c0, c1);
            *(float2*)&sP[(g + 8) * PSTR_ + n0 + (t4 << 1)] = make_float2(c2, c3);
        }
        __syncthreads();

        // online softmax (SIMT): 16 lanes per query row; zero invalid entries
        {
            float lm = -1e30f;
            #pragma unroll
            for (int j = 0; j < 8; ++j) {
                const int t = tt + (j << 4);
                const bool valid = (t < rows) && (t0 + t - LC_ <= ts);
                if (valid) lm = fmaxf(lm, sP[ts * PSTR_ + t]);
            }
            #pragma unroll
            for (int o = 8; o >= 1; o >>= 1)
                lm = fmaxf(lm, __shfl_xor_sync(0xffffffffu, lm, o));
            const float mold = sM[ts];
            const float mnew = fmaxf(mold, lm);
            float ls = 0.f;
            #pragma unroll
            for (int j = 0; j < 8; ++j) {
                const int t = tt + (j << 4);
                const bool valid = (t < rows) && (t0 + t - LC_ <= ts);
                float p = 0.f;
                if (valid) p = __expf(sP[ts * PSTR_ + t] - mnew);
                sP[ts * PSTR_ + t] = p;     // masked -> 0 so PV mma adds nothing
                ls += p;
            }
            #pragma unroll
            for (int o = 8; o >= 1; o >>= 1)
                ls += __shfl_xor_sync(0xffffffffu, ls, o);
            if (tt == 0) {
                const float fac = __expf(mold - mnew);
                sL[ts] = sL[ts] * fac + ls;
                sM[ts] = mnew;
                sF[ts] = fac;
            }
        }
        __syncthreads();

        // PV via mma: warp w computes output cols [8w, 8w+8), k = 128 timesteps
        {
            const int n0 = w << 3;
            const float f0 = sF[g], f1 = sF[g + 8];
            oc0 *= f0; oc1 *= f0; oc2 *= f1; oc3 *= f1;
            #pragma unroll
            for (int ks = 0; ks < 16; ++ks) {
                const unsigned a0 = toTF32(sP[g * PSTR_       + ks * 8 + t4]);
                const unsigned a1 = toTF32(sP[(g + 8) * PSTR_ + ks * 8 + t4]);
                const unsigned a2 = toTF32(sP[g * PSTR_       + ks * 8 + t4 + 4]);
                const unsigned a3 = toTF32(sP[(g + 8) * PSTR_ + ks * 8 + t4 + 4]);
                const unsigned b0 = toTF32(bV[(ks * 8 + t4) * KSTR_     + n0 + g]);
                const unsigned b1 = toTF32(bV[(ks * 8 + t4 + 4) * KSTR_ + n0 + g]);
                mma_tf32(oc0, oc1, oc2, oc3, a0, a1, a2, a3, b0, b1);
            }
        }
        __syncthreads();   // protect bK/bV/sP before next issue overwrites
    }

    // epilogue: divide by row sums, write ctx
    {
        const int n0 = w << 3;
        const float inv0 = 1.f / sL[g];
        const float inv1 = 1.f / sL[g + 8];
        const int col = h * DH_ + n0 + (t4 << 1);
        *(float2*)&g_ctx[(size_t)(g * B_ + b) * D_ + col] =
            make_float2(oc0 * inv0, oc1 * inv0);
        *(float2*)&g_ctx[(size_t)((g + 8) * B_ + b) * D_ + col] =
            make_float2(oc2 * inv1, oc3 * inv1);
    }
}

// ---------------- output projection: res = ctx @ Wo ----------------
__global__ void __launch_bounds__(256)
oproj_kernel(const float* __restrict__ Wo, float* __restrict__ out)
{
    const int r0 = blockIdx.y * 16;
    const int c0 = blockIdx.x * 64;
    __shared__ __align__(16) float As[16][KSTR_];
    __shared__ __align__(16) float Ws[64][KSTR_];
    const int tid = threadIdx.x;
    const int r  = tid & 15;
    const int c4 = tid >> 4;
    float ax = 0.f, ay = 0.f, az = 0.f, aw = 0.f;
    for (int k0 = 0; k0 < D_; k0 += 64) {
        {
            const int rr = tid >> 4, cc = (tid & 15) << 2;
            const float4 v = *(const float4*)&g_ctx[(size_t)(r0 + rr) * D_ + k0 + cc];
            *(float4*)&As[rr][cc] = v;
        }
        #pragma unroll
        for (int i = 0; i < 4; ++i) {
            const int rr = i * 16 + (tid >> 4), cc = (tid & 15) << 2;
            const float4 v = *(const float4*)&Wo[(size_t)(k0 + rr) * D_ + c0 + cc];
            *(float4*)&Ws[rr][cc] = v;
        }
        __syncthreads();
        #pragma unroll
        for (int kk = 0; kk < 64; kk += 4) {
            const float4 a4 = *(const float4*)&As[r][kk];
            #pragma unroll
            for (int u = 0; u < 4; ++u) {
                const float a = (u == 0) ? a4.x : (u == 1) ? a4.y : (u == 2) ? a4.z : a4.w;
                const float4 w = *(const float4*)&Ws[kk + u][c4 << 2];
                ax += a * w.x; ay += a * w.y; az += a * w.z; aw += a * w.w;
            }
        }
        __syncthreads();
    }
    *(float4*)&out[(size_t)(r0 + r) * D_ + c0 + (c4 << 2)] =
        make_float4(ax, ay, az, aw);
}

#define SMEM_ATTN_BYTES ((S_*DH_ + 4*CH_*KSTR_ + S_*PSTR_ + 48) * 4)

extern "C" void kernel_launch(void* const* d_in, const int* in_sizes, int n_in,
                              void* d_out, int out_size)
{
    const float* x  = (const float*)d_in[0];
    const float* ck = (const float*)d_in[1];
    const float* cv = (const float*)d_in[2];
    const float* Wq = (const float*)d_in[3];
    const float* Wk = (const float*)d_in[4];
    const float* Wv = (const float*)d_in[5];
    const float* Wo = (const float*)d_in[6];
    float* out = (float*)d_out;

    cudaFuncSetAttribute(attn_kernel,
        cudaFuncAttributeMaxDynamicSharedMemorySize, SMEM_ATTN_BYTES);

    qkv_kernel<<<dim3(16, 8, 3), 256>>>(x, Wq, Wk, Wv, out);
    attn_kernel<<<B_ * H_, 256, SMEM_ATTN_BYTES>>>(ck, cv, out);
    oproj_kernel<<<dim3(16, 8), 256>>>(Wo, out);
}

// round 4
// speedup vs baseline: 2.1925x; 1.1013x over previous
#include <cuda_runtime.h>
#include <math.h>

#define S_   16
#define B_   8
#define H_   16
#define DH_  64
#define D_   1024
#define LC_  8192
#define LT_  8208
#define CH_  128
#define NCH_ 65
#define KSTR_ 68
#define PSTR_ 132
#define ROWSTRIDE_ 8192
#define KOFF_ 131072
#define VOFF_ (131072 + 67239936)

__device__ float g_q[S_ * B_ * D_];
__device__ float g_ctx[S_ * B_ * D_];

// ---------------- cp.async helpers ----------------
__device__ __forceinline__ void cp_async16(unsigned saddr, const void* gptr) {
    asm volatile("cp.async.cg.shared.global [%0], [%1], 16;" :: "r"(saddr), "l"(gptr));
}
__device__ __forceinline__ void cp_commit() {
    asm volatile("cp.async.commit_group;" ::: "memory");
}
template <int N> __device__ __forceinline__ void cp_wait() {
    asm volatile("cp.async.wait_group %0;" :: "n"(N) : "memory");
}
__device__ __forceinline__ unsigned smem_u32(const void* p) {
    return (unsigned)__cvta_generic_to_shared(p);
}

// ---------------- tf32 mma helpers ----------------
__device__ __forceinline__ unsigned toTF32(float x) {
    unsigned r;
    asm("cvt.rna.tf32.f32 %0, %1;" : "=r"(r) : "f"(x));
    return r;
}
__device__ __forceinline__ void mma_tf32(float& c0, float& c1, float& c2, float& c3,
                                         unsigned a0, unsigned a1, unsigned a2, unsigned a3,
                                         unsigned b0, unsigned b1) {
    asm volatile(
        "mma.sync.aligned.m16n8k8.row.col.f32.tf32.tf32.f32 "
        "{%0,%1,%2,%3},{%4,%5,%6,%7},{%8,%9},{%0,%1,%2,%3};"
        : "+f"(c0), "+f"(c1), "+f"(c2), "+f"(c3)
        : "r"(a0), "r"(a1), "r"(a2), "r"(a3), "r"(b0), "r"(b1));
}

// ---------------- f32x2 packed FMA helpers ----------------
__device__ __forceinline__ unsigned long long pack2(float a) {
    unsigned long long p;
    asm("mov.b64 %0, {%1, %1};" : "=l"(p) : "f"(a));
    return p;
}
__device__ __forceinline__ void ffma2(unsigned long long& c,
                                      unsigned long long a, unsigned long long b) {
    asm("fma.rn.f32x2 %0, %1, %2, %0;" : "+l"(c) : "l"(a), "l"(b));
}
__device__ __forceinline__ float2 unpack2(unsigned long long c) {
    float x, y;
    asm("mov.b64 {%0, %1}, %2;" : "=f"(x), "=f"(y) : "l"(c));
    return make_float2(x, y);
}

// ---------------- QKV projection: 64x64 tile, f32x2 FMA ----------------
// grid (16, 2, 3), block 256. Exact fp32 rounding (fma.rn.f32x2 == 2x FFMA).
__global__ void __launch_bounds__(256)
qkv_kernel(const float* __restrict__ x,
           const float* __restrict__ Wq, const float* __restrict__ Wk,
           const float* __restrict__ Wv, float* __restrict__ out)
{
    const int mat = blockIdx.z;
    const float* __restrict__ W = (mat == 0) ? Wq : (mat == 1) ? Wk : Wv;
    const int r0 = blockIdx.y * 64;
    const int c0 = blockIdx.x * 64;

    __shared__ __align__(16) float As[2][16][KSTR_];   // [k][m] transposed
    __shared__ __align__(16) float Bs[2][16][KSTR_];   // [k][n]

    const int tid = threadIdx.x;
    const int ty = tid >> 4;        // micro-tile row group (m = ty*4..)
    const int tx = tid & 15;        // micro-tile col group (n = tx*4..)

    // global-load index split
    const int am = tid >> 2, ak = (tid & 3) << 2;      // A: 64 rows x 16 k
    const int bk = tid >> 4, bn = (tid & 15) << 2;     // B: 16 k x 64 n

    unsigned long long c01[4] = {0ull, 0ull, 0ull, 0ull};
    unsigned long long c23[4] = {0ull, 0ull, 0ull, 0ull};

    float4 rA = *(const float4*)&x[(size_t)(r0 + am) * D_ + ak];
    float4 rB = *(const float4*)&W[(size_t)bk * D_ + c0 + bn];
    // stage kt=0
    As[0][ak + 0][am] = rA.x; As[0][ak + 1][am] = rA.y;
    As[0][ak + 2][am] = rA.z; As[0][ak + 3][am] = rA.w;
    *(float4*)&Bs[0][bk][bn] = rB;
    __syncthreads();

    for (int kt = 0; kt < 64; ++kt) {
        const int buf = kt & 1;
        if (kt < 63) {
            const int k0 = (kt + 1) * 16;
            rA = *(const float4*)&x[(size_t)(r0 + am) * D_ + k0 + ak];
            rB = *(const float4*)&W[(size_t)(k0 + bk) * D_ + c0 + bn];
        }
        #pragma unroll
        for (int k = 0; k < 16; ++k) {
            const float4 a4 = *(const float4*)&As[buf][k][ty << 2];
            const ulonglong2 bp = *(const ulonglong2*)&Bs[buf][k][tx << 2];
            const unsigned long long p0 = pack2(a4.x), p1 = pack2(a4.y);
            const unsigned long long p2 = pack2(a4.z), p3 = pack2(a4.w);
            ffma2(c01[0], p0, bp.x); ffma2(c23[0], p0, bp.y);
            ffma2(c01[1], p1, bp.x); ffma2(c23[1], p1, bp.y);
            ffma2(c01[2], p2, bp.x); ffma2(c23[2], p2, bp.y);
            ffma2(c01[3], p3, bp.x); ffma2(c23[3], p3, bp.y);
        }
        if (kt < 63) {
            const int nb = buf ^ 1;
            As[nb][ak + 0][am] = rA.x; As[nb][ak + 1][am] = rA.y;
            As[nb][ak + 2][am] = rA.z; As[nb][ak + 3][am] = rA.w;
            *(float4*)&Bs[nb][bk][bn] = rB;
        }
        __syncthreads();
    }

    #pragma unroll
    for (int r = 0; r < 4; ++r) {
        const int row = r0 + (ty << 2) + r;      // row = s*B + b
        const int s = row >> 3, b = row & 7;
        const int col = c0 + (tx << 2);
        const float2 lo = unpack2(c01[r]);
        const float2 hi = unpack2(c23[r]);
        const float4 res = make_float4(lo.x, lo.y, hi.x, hi.y);
        if (mat == 0) {
            *(float4*)&g_q[(size_t)row * D_ + col] = res;
        } else {
            float* dst = out + ((mat == 1) ? KOFF_ : VOFF_);
            *(float4*)&dst[(size_t)(LC_ + s) * ROWSTRIDE_ + b * D_ + col] = res;
        }
    }
}

// ---------------- fused attention + cache copy (tf32 mma) ----------------
__global__ void __launch_bounds__(256, 1)
attn_kernel(const float* __restrict__ cK, const float* __restrict__ cV,
            float* __restrict__ out)
{
    extern __shared__ __align__(16) float sh[];
    float* sQ  = sh;
    float* sK0 = sQ  + S_ * DH_;
    float* sV0 = sK0 + CH_ * KSTR_;
    float* sK1 = sV0 + CH_ * KSTR_;
    float* sV1 = sK1 + CH_ * KSTR_;
    float* sP  = sV1 + CH_ * KSTR_;
    float* sM  = sP  + S_ * PSTR_;
    float* sL  = sM + 16;
    float* sF  = sL + 16;

    const int tid  = threadIdx.x;
    const int lane = tid & 31;
    const int w    = tid >> 5;
    const int bh   = blockIdx.x;
    const int b    = bh >> 4, h = bh & 15;
    const int ts   = tid >> 4;
    const int tt   = tid & 15;
    const int g    = lane >> 2;
    const int t4   = lane & 3;

    {   // load Q, pre-scaled by 1/sqrt(DH)
        const float4 q4 = *(const float4*)&g_q[(size_t)(ts * B_ + b) * D_ + h * DH_ + (tt << 2)];
        float* dst = &sQ[ts * DH_ + (tt << 2)];
        dst[0] = q4.x * 0.125f; dst[1] = q4.y * 0.125f;
        dst[2] = q4.z * 0.125f; dst[3] = q4.w * 0.125f;
    }
    if (tid < 16) { sM[tid] = -1e30f; sL[tid] = 0.f; }

    float* outK = out + KOFF_;
    float* outV = out + VOFF_;
    const size_t baseBH = (size_t)bh * DH_;

    auto issue = [&](int c, float* dK, float* dV) {
        const int t0 = c * CH_;
        const int n = (t0 + CH_ <= LT_ ? CH_ : LT_ - t0) * 16;
        for (int idx = tid; idx < n; idx += 256) {
            const int r = idx >> 4, f = (idx & 15) << 2;
            const int t = t0 + r;
            const size_t gg = (size_t)t * ROWSTRIDE_ + baseBH + f;
            const float* srcK = (t < LC_) ? (cK + gg) : (outK + gg);
            const float* srcV = (t < LC_) ? (cV + gg) : (outV + gg);
            cp_async16(smem_u32(&dK[r * KSTR_ + f]), srcK);
            cp_async16(smem_u32(&dV[r * KSTR_ + f]), srcV);
        }
        cp_commit();
    };

    issue(0, sK0, sV0);
    __syncthreads();

    // Q fragments (every warp holds full 16x64 Q)
    unsigned qA[8][4];
    #pragma unroll
    for (int ks = 0; ks < 8; ++ks) {
        qA[ks][0] = toTF32(sQ[g * DH_       + ks * 8 + t4]);
        qA[ks][1] = toTF32(sQ[(g + 8) * DH_ + ks * 8 + t4]);
        qA[ks][2] = toTF32(sQ[g * DH_       + ks * 8 + t4 + 4]);
        qA[ks][3] = toTF32(sQ[(g + 8) * DH_ + ks * 8 + t4 + 4]);
    }

    // PV accumulators: warps 0-3 own output cols [16w, 16w+16) as 2 n-tiles
    float oc[2][4] = {{0.f,0.f,0.f,0.f},{0.f,0.f,0.f,0.f}};

    for (int c = 0; c < NCH_; ++c) {
        float* bK = (c & 1) ? sK1 : sK0;
        float* bV = (c & 1) ? sV1 : sV0;
        if (c + 1 < NCH_) {
            issue(c + 1, (c & 1) ? sK0 : sK1, (c & 1) ? sV0 : sV1);
            cp_wait<1>();
        } else {
            cp_wait<0>();
        }
        __syncthreads();

        const int t0   = c * CH_;
        const int rows = (t0 + CH_ <= LT_) ? CH_ : (LT_ - t0);

        // scores via mma: warp w computes cols [16w, 16w+16)
        #pragma unroll
        for (int nt = 0; nt < 2; ++nt) {
            const int n0 = (w << 4) + (nt << 3);
            float c0 = 0.f, c1 = 0.f, c2 = 0.f, c3 = 0.f;
            #pragma unroll
            for (int ks = 0; ks < 8; ++ks) {
                const unsigned b0 = toTF32(bK[(n0 + g) * KSTR_ + ks * 8 + t4]);
                const unsigned b1 = toTF32(bK[(n0 + g) * KSTR_ + ks * 8 + t4 + 4]);
                mma_tf32(c0, c1, c2, c3,
                         qA[ks][0], qA[ks][1], qA[ks][2], qA[ks][3], b0, b1);
            }
            *(float2*)&sP[g * PSTR_       + n0 + (t4 << 1)] = make_float2(c0, c1);
            *(float2*)&sP[(g + 8) * PSTR_ + n0 + (t4 << 1)] = make_float2(c2, c3);
        }
        __syncthreads();

        // online softmax; store P pre-rounded to tf32 (masked -> 0)
        {
            float lm = -1e30f;
            #pragma unroll
            for (int j = 0; j < 8; ++j) {
                const int t = tt + (j << 4);
                const bool valid = (t < rows) && (t0 + t - LC_ <= ts);
                if (valid) lm = fmaxf(lm, sP[ts * PSTR_ + t]);
            }
            #pragma unroll
            for (int o = 8; o >= 1; o >>= 1)
                lm = fmaxf(lm, __shfl_xor_sync(0xffffffffu, lm, o));
            const float mold = sM[ts];
            const float mnew = fmaxf(mold, lm);
            float ls = 0.f;
            #pragma unroll
            for (int j = 0; j < 8; ++j) {
                const int t = tt + (j << 4);
                const bool valid = (t < rows) && (t0 + t - LC_ <= ts);
                float p = 0.f;
                if (valid) p = __expf(sP[ts * PSTR_ + t] - mnew);
                sP[ts * PSTR_ + t] = __uint_as_float(toTF32(p));
                ls += p;
            }
            #pragma unroll
            for (int o = 8; o >= 1; o >>= 1)
                ls += __shfl_xor_sync(0xffffffffu, ls, o);
            if (tt == 0) {
                const float fac = __expf(mold - mnew);
                sL[ts] = sL[ts] * fac + ls;
                sM[ts] = mnew;
                sF[ts] = fac;
            }
        }
        __syncthreads();

        // phase 3 (warp-specialized): warps 0-3 PV, warps 4-7 cache copy
        if (w < 4) {
            const float f0 = sF[g], f1 = sF[g + 8];
            #pragma unroll
            for (int nt = 0; nt < 2; ++nt) {
                oc[nt][0] *= f0; oc[nt][1] *= f0;
                oc[nt][2] *= f1; oc[nt][3] *= f1;
            }
            #pragma unroll
            for (int ks = 0; ks < 16; ++ks) {
                // P already tf32-rounded: reinterpret bits
                const unsigned a0 = __float_as_uint(sP[g * PSTR_       + ks * 8 + t4]);
                const unsigned a1 = __float_as_uint(sP[(g + 8) * PSTR_ + ks * 8 + t4]);
                const unsigned a2 = __float_as_uint(sP[g * PSTR_       + ks * 8 + t4 + 4]);
                const unsigned a3 = __float_as_uint(sP[(g + 8) * PSTR_ + ks * 8 + t4 + 4]);
                #pragma unroll
                for (int nt = 0; nt < 2; ++nt) {
                    const int n0 = (w << 4) + (nt << 3);
                    const unsigned b0 = toTF32(bV[(ks * 8 + t4) * KSTR_     + n0 + g]);
                    const unsigned b1 = toTF32(bV[(ks * 8 + t4 + 4) * KSTR_ + n0 + g]);
                    mma_tf32(oc[nt][0], oc[nt][1], oc[nt][2], oc[nt][3],
                             a0, a1, a2, a3, b0, b1);
                }
            }
        } else if (t0 < LC_) {
            for (int idx = tid - 128; idx < CH_ * 16; idx += 128) {
                const int r = idx >> 4, f = (idx & 15) << 2;
                const size_t gg = (size_t)(t0 + r) * ROWSTRIDE_ + baseBH + f;
                *(float4*)&outK[gg] = *(const float4*)&bK[r * KSTR_ + f];
                *(float4*)&outV[gg] = *(const float4*)&bV[r * KSTR_ + f];
            }
        }
        __syncthreads();
    }

    // epilogue: warps 0-3 write ctx
    if (w < 4) {
        const float inv0 = 1.f / sL[g];
        const float inv1 = 1.f / sL[g + 8];
        #pragma unroll
        for (int nt = 0; nt < 2; ++nt) {
            const int n0 = (w << 4) + (nt << 3);
            const int col = h * DH_ + n0 + (t4 << 1);
            *(float2*)&g_ctx[(size_t)(g * B_ + b) * D_ + col] =
                make_float2(oc[nt][0] * inv0, oc[nt][1] * inv0);
            *(float2*)&g_ctx[(size_t)((g + 8) * B_ + b) * D_ + col] =
                make_float2(oc[nt][2] * inv1, oc[nt][3] * inv1);
        }
    }
}

// ---------------- output projection: res = ctx @ Wo ----------------
__global__ void __launch_bounds__(256)
oproj_kernel(const float* __restrict__ Wo, float* __restrict__ out)
{
    const int r0 = blockIdx.y * 16;
    const int c0 = blockIdx.x * 64;
    __shared__ __align__(16) float As[16][KSTR_];
    __shared__ __align__(16) float Ws[64][KSTR_];
    const int tid = threadIdx.x;
    const int r  = tid & 15;
    const int c4 = tid >> 4;
    float ax = 0.f, ay = 0.f, az = 0.f, aw = 0.f;
    for (int k0 = 0; k0 < D_; k0 += 64) {
        {
            const int rr = tid >> 4, cc = (tid & 15) << 2;
            const float4 v = *(const float4*)&g_ctx[(size_t)(r0 + rr) * D_ + k0 + cc];
            *(float4*)&As[rr][cc] = v;
        }
        #pragma unroll
        for (int i = 0; i < 4; ++i) {
            const int rr = i * 16 + (tid >> 4), cc = (tid & 15) << 2;
            const float4 v = *(const float4*)&Wo[(size_t)(k0 + rr) * D_ + c0 + cc];
            *(float4*)&Ws[rr][cc] = v;
        }
        __syncthreads();
        #pragma unroll
        for (int kk = 0; kk < 64; kk += 4) {
            const float4 a4 = *(const float4*)&As[r][kk];
            #pragma unroll
            for (int u = 0; u < 4; ++u) {
                const float a = (u == 0) ? a4.x : (u == 1) ? a4.y : (u == 2) ? a4.z : a4.w;
                const float4 w = *(const float4*)&Ws[kk + u][c4 << 2];
                ax += a * w.x; ay += a * w.y; az += a * w.z; aw += a * w.w;
            }
        }
        __syncthreads();
    }
    *(float4*)&out[(size_t)(r0 + r) * D_ + c0 + (c4 << 2)] =
        make_float4(ax, ay, az, aw);
}

#define SMEM_ATTN_BYTES ((S_*DH_ + 4*CH_*KSTR_ + S_*PSTR_ + 48) * 4)

extern "C" void kernel_launch(void* const* d_in, const int* in_sizes, int n_in,
                              void* d_out, int out_size)
{
    const float* x  = (const float*)d_in[0];
    const float* ck = (const float*)d_in[1];
    const float* cv = (const float*)d_in[2];
    const float* Wq = (const float*)d_in[3];
    const float* Wk = (const float*)d_in[4];
    const float* Wv = (const float*)d_in[5];
    const float* Wo = (const float*)d_in[6];
    float* out = (float*)d_out;

    cudaFuncSetAttribute(attn_kernel,
        cudaFuncAttributeMaxDynamicSharedMemorySize, SMEM_ATTN_BYTES);

    qkv_kernel<<<dim3(16, 2, 3), 256>>>(x, Wq, Wk, Wv, out);
    attn_kernel<<<B_ * H_, 256, SMEM_ATTN_BYTES>>>(ck, cv, out);
    oproj_kernel<<<dim3(16, 8), 256>>>(Wo, out);
}